// round 2
// baseline (speedup 1.0000x reference)
#include <cuda_runtime.h>
#include <math.h>

#define BB 64
#define TT 128
#define DD 512
#define NBD (BB*DD)        /* 32768 */
#define BTD (BB*TT*DD)     /* 4194304 */

// ---------------- device state ----------------
__device__ float g_Q[TT*NBD];
__device__ float g_K[TT*NBD];
__device__ float g_V[TT*NBD];
__device__ float g_th[TT], g_et[TT], g_al[TT];
__device__ float g_W1[DD*DD], g_M1w[DD*DD], g_b1[DD], g_M1b[DD];
__device__ float g_W2[DD*DD], g_M2w[DD*DD], g_b2[DD], g_M2b[DD];
__device__ float g_h[2*NBD];      // raw pre-activations: rows 0-63 q-path, 64-127 k-path
__device__ float g_diff[NBD];     // out - v (UNSCALED)
__device__ float g_dpre[NBD];     // masked diff@W2 (UNSCALED)
__device__ float g_gW1[DD*DD], g_gW2[DD*DD];
__device__ float g_loss[TT];      // sum of squared diffs (not yet /N)

// ---------------- init: copy weights, zero momentum + loss ----------------
__global__ void k_init(const float* __restrict__ W1, const float* __restrict__ b1,
                       const float* __restrict__ W2, const float* __restrict__ b2) {
    int i = blockIdx.x * 256 + threadIdx.x;
    if (i < DD*DD) { g_W1[i] = W1[i]; g_M1w[i] = 0.f; g_W2[i] = W2[i]; g_M2w[i] = 0.f; }
    if (i < DD)    { g_b1[i] = b1[i]; g_M1b[i] = 0.f; g_b2[i] = b2[i]; g_M2b[i] = 0.f; }
    if (i < TT)    g_loss[i] = 0.f;
}

// ---------------- gates: mean_b sigmoid(x_t . w + b) for theta/eta/alpha ----------------
__global__ void k_gates(const float* __restrict__ x,
                        const float* __restrict__ thw, const float* __restrict__ thb,
                        const float* __restrict__ etw, const float* __restrict__ etb,
                        const float* __restrict__ alw, const float* __restrict__ alb) {
    int t = blockIdx.x, tid = threadIdx.x, lane = tid & 31, warp = tid >> 5;
    __shared__ float red[8];
    for (int g = 0; g < 3; g++) {
        const float* w = (g == 0) ? thw : ((g == 1) ? etw : alw);
        float b0 = (g == 0) ? thb[0] : ((g == 1) ? etb[0] : alb[0]);
        float acc = 0.f;
        for (int bi = warp; bi < BB; bi += 8) {
            const float* xr = x + ((size_t)bi * TT + t) * DD;
            float s = 0.f;
            for (int k = lane; k < DD; k += 32) s += xr[k] * w[k];
            #pragma unroll
            for (int o = 16; o; o >>= 1) s += __shfl_down_sync(0xffffffffu, s, o);
            if (lane == 0) acc += 1.f / (1.f + expf(-(s + b0)));
        }
        if (lane == 0) red[warp] = acc;
        __syncthreads();
        if (tid == 0) {
            float s = 0.f;
            #pragma unroll
            for (int i = 0; i < 8; i++) s += red[i];
            s *= (1.f / (float)BB);
            if (g == 0) g_th[t] = s; else if (g == 1) g_et[t] = s; else g_al[t] = s;
        }
        __syncthreads();
    }
}

// ---------------- QKV: g_{Q,K,V}[t][b][n] = sum_k x[b][t][k] * W[n][k] ----------------
__global__ __launch_bounds__(256) void k_qkv(const float* __restrict__ x,
                       const float* __restrict__ WQ, const float* __restrict__ WK,
                       const float* __restrict__ WV) {
    __shared__ float As[32][33], Bs[32][33];
    int n0 = blockIdx.x * 32, m0 = blockIdx.y * 32;
    const float* W = (blockIdx.z == 0) ? WQ : ((blockIdx.z == 1) ? WK : WV);
    float* O = (blockIdx.z == 0) ? g_Q : ((blockIdx.z == 1) ? g_K : g_V);
    int tx = threadIdx.x & 15, ty = threadIdx.x >> 4;
    float a00 = 0.f, a01 = 0.f, a10 = 0.f, a11 = 0.f;
    for (int k0 = 0; k0 < DD; k0 += 32) {
        for (int i = threadIdx.x; i < 1024; i += 256) {
            int r = i >> 5, c = i & 31;
            int m = m0 + r, t = m >> 6, b = m & 63;
            As[r][c] = x[((size_t)b * TT + t) * DD + k0 + c];
            Bs[r][c] = W[(size_t)(n0 + r) * DD + k0 + c];
        }
        __syncthreads();
        #pragma unroll
        for (int k = 0; k < 32; k++) {
            float x0 = As[ty*2][k], x1 = As[ty*2+1][k];
            float y0 = Bs[tx*2][k], y1 = Bs[tx*2+1][k];
            a00 += x0*y0; a01 += x0*y1; a10 += x1*y0; a11 += x1*y1;
        }
        __syncthreads();
    }
    int m = m0 + ty*2, n = n0 + tx*2;
    O[(size_t)m*DD + n] = a00;       O[(size_t)m*DD + n + 1] = a01;
    O[(size_t)(m+1)*DD + n] = a10;   O[(size_t)(m+1)*DD + n + 1] = a11;
}

// ---------------- per-step: h_raw = [q;k] @ W1^T + b1 ----------------
__global__ __launch_bounds__(256) void k_h(int t) {
    __shared__ float As[32][33], Bs[32][33];
    int n0 = blockIdx.x * 32, m0 = blockIdx.y * 32;
    int tx = threadIdx.x & 15, ty = threadIdx.x >> 4;
    const float* Qt = g_Q + (size_t)t * NBD;
    const float* Kt = g_K + (size_t)t * NBD;
    float a00 = 0.f, a01 = 0.f, a10 = 0.f, a11 = 0.f;
    for (int k0 = 0; k0 < DD; k0 += 32) {
        for (int i = threadIdx.x; i < 1024; i += 256) {
            int r = i >> 5, c = i & 31, m = m0 + r;
            As[r][c] = (m < 64) ? Qt[(size_t)m*DD + k0 + c] : Kt[(size_t)(m-64)*DD + k0 + c];
            Bs[r][c] = g_W1[(size_t)(n0 + r)*DD + k0 + c];
        }
        __syncthreads();
        #pragma unroll
        for (int k = 0; k < 32; k++) {
            float x0 = As[ty*2][k], x1 = As[ty*2+1][k];
            float y0 = Bs[tx*2][k], y1 = Bs[tx*2+1][k];
            a00 += x0*y0; a01 += x0*y1; a10 += x1*y0; a11 += x1*y1;
        }
        __syncthreads();
    }
    int m = m0 + ty*2, n = n0 + tx*2;
    float bb0 = g_b1[n], bb1 = g_b1[n+1];
    g_h[(size_t)m*DD + n] = a00 + bb0;       g_h[(size_t)m*DD + n + 1] = a01 + bb1;
    g_h[(size_t)(m+1)*DD + n] = a10 + bb0;   g_h[(size_t)(m+1)*DD + n + 1] = a11 + bb1;
}

// ---------------- per-step: out = relu(h_raw) @ W2^T + b2 -> mem output / diff / loss ----
__global__ __launch_bounds__(256) void k_out(int t, float* __restrict__ out, int dup) {
    __shared__ float As[32][33], Bs[32][33];
    __shared__ float red[8];
    int n0 = blockIdx.x * 32, m0 = blockIdx.y * 32;
    int tx = threadIdx.x & 15, ty = threadIdx.x >> 4;
    float a00 = 0.f, a01 = 0.f, a10 = 0.f, a11 = 0.f;
    for (int k0 = 0; k0 < DD; k0 += 32) {
        for (int i = threadIdx.x; i < 1024; i += 256) {
            int r = i >> 5, c = i & 31;
            As[r][c] = fmaxf(g_h[(size_t)(m0 + r)*DD + k0 + c], 0.f);
            Bs[r][c] = g_W2[(size_t)(n0 + r)*DD + k0 + c];
        }
        __syncthreads();
        #pragma unroll
        for (int k = 0; k < 32; k++) {
            float x0 = As[ty*2][k], x1 = As[ty*2+1][k];
            float y0 = Bs[tx*2][k], y1 = Bs[tx*2+1][k];
            a00 += x0*y0; a01 += x0*y1; a10 += x1*y0; a11 += x1*y1;
        }
        __syncthreads();
    }
    int m = m0 + ty*2, n = n0 + tx*2;
    float bb0 = g_b2[n], bb1 = g_b2[n+1];
    a00 += bb0; a01 += bb1; a10 += bb0; a11 += bb1;
    float lsum = 0.f;
    if (m < 64) {  // q-path: memory output
        size_t o0 = ((size_t)m*TT + t)*DD + n;
        size_t o1 = ((size_t)(m+1)*TT + t)*DD + n;
        out[o0] = a00; out[o0+1] = a01; out[o1] = a10; out[o1+1] = a11;
        if (dup) { out[BTD+o0] = a00; out[BTD+o0+1] = a01; out[BTD+o1] = a10; out[BTD+o1+1] = a11; }
    } else {       // k-path: diff + loss
        int b = m - 64;
        const float* vp0 = g_V + (size_t)t*NBD + (size_t)b*DD + n;
        const float* vp1 = vp0 + DD;
        float d0 = a00 - vp0[0], d1 = a01 - vp0[1];
        float d2 = a10 - vp1[0], d3 = a11 - vp1[1];
        float* dp = g_diff + (size_t)b*DD + n;
        dp[0] = d0; dp[1] = d1; dp[DD] = d2; dp[DD+1] = d3;
        lsum = d0*d0 + d1*d1 + d2*d2 + d3*d3;
    }
    if (m0 >= 64) {
        #pragma unroll
        for (int o = 16; o; o >>= 1) lsum += __shfl_down_sync(0xffffffffu, lsum, o);
        if ((threadIdx.x & 31) == 0) red[threadIdx.x >> 5] = lsum;
        __syncthreads();
        if (threadIdx.x == 0) {
            float s = 0.f;
            #pragma unroll
            for (int i = 0; i < 8; i++) s += red[i];
            atomicAdd(&g_loss[t], s);
        }
    }
}

// ---------------- per-step: dpre = mask(hpre_k>0) * (diff @ W2)  (UNSCALED) ----------------
__global__ __launch_bounds__(256) void k_dpre(int t) {
    __shared__ float As[32][33], Bs[32][33];
    int n0 = blockIdx.x * 32, m0 = blockIdx.y * 32;
    int tx = threadIdx.x & 15, ty = threadIdx.x >> 4;
    float a00 = 0.f, a01 = 0.f, a10 = 0.f, a11 = 0.f;
    for (int k0 = 0; k0 < DD; k0 += 32) {
        for (int i = threadIdx.x; i < 1024; i += 256) {
            int r = i >> 5, c = i & 31;
            As[r][c] = g_diff[(size_t)(m0 + r)*DD + k0 + c];
            Bs[r][c] = g_W2[(size_t)(k0 + r)*DD + n0 + c];
        }
        __syncthreads();
        #pragma unroll
        for (int k = 0; k < 32; k++) {
            float x0 = As[ty*2][k], x1 = As[ty*2+1][k];
            float y0 = Bs[k][tx*2], y1 = Bs[k][tx*2+1];
            a00 += x0*y0; a01 += x0*y1; a10 += x1*y0; a11 += x1*y1;
        }
        __syncthreads();
    }
    int m = m0 + ty*2, n = n0 + tx*2;
    const float* hp0 = g_h + (size_t)(64 + m)*DD + n;
    const float* hp1 = hp0 + DD;
    float* dp = g_dpre + (size_t)m*DD + n;
    dp[0]    = (hp0[0] > 0.f) ? a00 : 0.f;
    dp[1]    = (hp0[1] > 0.f) ? a01 : 0.f;
    dp[DD]   = (hp1[0] > 0.f) ? a10 : 0.f;
    dp[DD+1] = (hp1[1] > 0.f) ? a11 : 0.f;
}

// ---------------- per-step: gW1 = dpre^T @ k ; gW2 = diff^T @ relu(h_k)  (UNSCALED) -------
__global__ __launch_bounds__(256) void k_grads(int t) {
    __shared__ float As[32][33], Bs[32][33];
    int j0 = blockIdx.x * 32, i0 = blockIdx.y * 32;
    int tx = threadIdx.x & 15, ty = threadIdx.x >> 4;
    const float* A = (blockIdx.z == 0) ? g_dpre : g_diff;
    float a00 = 0.f, a01 = 0.f, a10 = 0.f, a11 = 0.f;
    for (int k0 = 0; k0 < BB; k0 += 32) {
        for (int i = threadIdx.x; i < 1024; i += 256) {
            int r = i >> 5, c = i & 31;
            As[r][c] = A[(size_t)(k0 + r)*DD + i0 + c];
            if (blockIdx.z == 0)
                Bs[r][c] = g_K[(size_t)t*NBD + (size_t)(k0 + r)*DD + j0 + c];
            else
                Bs[r][c] = fmaxf(g_h[(size_t)(64 + k0 + r)*DD + j0 + c], 0.f);
        }
        __syncthreads();
        #pragma unroll
        for (int k = 0; k < 32; k++) {
            float x0 = As[k][ty*2], x1 = As[k][ty*2+1];
            float y0 = Bs[k][tx*2], y1 = Bs[k][tx*2+1];
            a00 += x0*y0; a01 += x0*y1; a10 += x1*y0; a11 += x1*y1;
        }
        __syncthreads();
    }
    int i = i0 + ty*2, j = j0 + tx*2;
    float* G = (blockIdx.z == 0) ? g_gW1 : g_gW2;
    G[(size_t)i*DD + j] = a00;       G[(size_t)i*DD + j + 1] = a01;
    G[(size_t)(i+1)*DD + j] = a10;   G[(size_t)(i+1)*DD + j + 1] = a11;
}

// ---------------- per-step: momentum + weight-decay update (scale applied here) -----------
__global__ void k_update(int t) {
    float th = g_th[t], et = g_et[t], al = g_al[t];
    float ls = g_loss[t] * (1.f / (float)NBD);
    float pt = (ls >= 1e-10f && ls <= 1e10f) ? 1.f : 0.f;
    float s = th * pt * (2.f / (float)NBD);
    float oa = 1.f - al;
    int bid = blockIdx.x;
    if (bid < 1024) {
        int i = bid * 256 + threadIdx.x;
        float m = et * g_M1w[i] - s * g_gW1[i];
        g_M1w[i] = m; g_W1[i] = oa * g_W1[i] + m;
    } else if (bid < 2048) {
        int i = (bid - 1024) * 256 + threadIdx.x;
        float m = et * g_M2w[i] - s * g_gW2[i];
        g_M2w[i] = m; g_W2[i] = oa * g_W2[i] + m;
    } else {
        int i = (bid - 2048) * 256 + threadIdx.x;  // 0..1023
        if (i < 512) {
            float g = 0.f;
            for (int b = 0; b < BB; b++) g += g_dpre[(size_t)b*DD + i];
            float m = et * g_M1b[i] - s * g;
            g_M1b[i] = m; g_b1[i] = oa * g_b1[i] + m;
        } else if (i < 1024) {
            int j = i - 512;
            float g = 0.f;
            for (int b = 0; b < BB; b++) g += g_diff[(size_t)b*DD + j];
            float m = et * g_M2b[j] - s * g;
            g_M2b[j] = m; g_b2[j] = oa * g_b2[j] + m;
        }
    }
}

// ---------------- launch ----------------
extern "C" void kernel_launch(void* const* d_in, const int* in_sizes, int n_in,
                              void* d_out, int out_size) {
    const float* x   = (const float*)d_in[0];
    const float* WQ  = (const float*)d_in[1];
    const float* WK  = (const float*)d_in[2];
    const float* WV  = (const float*)d_in[3];
    const float* thw = (const float*)d_in[4];
    const float* thb = (const float*)d_in[5];
    const float* etw = (const float*)d_in[6];
    const float* etb = (const float*)d_in[7];
    const float* alw = (const float*)d_in[8];
    const float* alb = (const float*)d_in[9];
    const float* W1  = (const float*)d_in[10];
    const float* b1  = (const float*)d_in[11];
    const float* W2  = (const float*)d_in[12];
    const float* b2  = (const float*)d_in[13];
    float* out = (float*)d_out;
    int dup = (out_size >= 2 * BTD) ? 1 : 0;

    k_init<<<1024, 256>>>(W1, b1, W2, b2);
    k_gates<<<TT, 256>>>(x, thw, thb, etw, etb, alw, alb);
    k_qkv<<<dim3(16, 256, 3), 256>>>(x, WQ, WK, WV);
    for (int t = 0; t < TT; t++) {
        k_h<<<dim3(16, 4), 256>>>(t);
        k_out<<<dim3(16, 4), 256>>>(t, out, dup);
        k_dpre<<<dim3(16, 2), 256>>>(t);
        k_grads<<<dim3(16, 16, 2), 256>>>(t);
        k_update<<<2052, 256>>>(t);
    }
}